// round 10
// baseline (speedup 1.0000x reference)
#include <cuda_runtime.h>
#include <math.h>

#define Bn 2
#define Nn 1024
#define Dn 64
#define SCHUNKS 16          // s-dimension split for msg_agg
#define TT 64               // t-tile per block in msg_agg
#define SC (Nn / SCHUNKS)   // 64 s per block
#define SA_STRIDE 68        // padded [s][t] stride, float4-aligned

typedef unsigned long long u64t;

// -------- scratch (no malloc allowed) --------
__device__ float g_ps[Bn * Nn * Dn];
__device__ float g_ptb[Bn * Nn * Dn];
__device__ float g_hpart[SCHUNKS * Bn * Nn * Dn];   // post-W2 partials

// ---------- packed f32x2 helpers ----------
__device__ __forceinline__ u64t pack2(float lo, float hi) {
    u64t r;
    asm("mov.b64 %0, {%1, %2};" : "=l"(r) : "f"(lo), "f"(hi));
    return r;
}
__device__ __forceinline__ void unpack2(u64t v, float& lo, float& hi) {
    asm("mov.b64 {%0, %1}, %2;" : "=f"(lo), "=f"(hi) : "l"(v));
}
__device__ __forceinline__ u64t add2(u64t a, u64t b) {
    u64t d;
    asm("add.rn.f32x2 %0, %1, %2;" : "=l"(d) : "l"(a), "l"(b));
    return d;
}
__device__ __forceinline__ u64t fma2(u64t a, u64t b, u64t c) {
    u64t d;
    asm("fma.rn.f32x2 %0, %1, %2, %3;" : "=l"(d) : "l"(a), "l"(b), "l"(c));
    return d;
}
__device__ __forceinline__ u64t relu2(u64t x) {
    u64t r;
    asm("{\n\t"
        ".reg .f32 lo, hi;\n\t"
        "mov.b64 {lo, hi}, %1;\n\t"
        "max.f32 lo, lo, 0f00000000;\n\t"
        "max.f32 hi, hi, 0f00000000;\n\t"
        "mov.b64 %0, {lo, hi};\n\t"
        "}" : "=l"(r) : "l"(x));
    return r;
}

// ============================================================
// K1: gumbel softmax, 4 rows per block (deep ILP), float4 I/O
// ============================================================
__global__ void __launch_bounds__(256) gumbel_softmax_kernel(
    const float* __restrict__ u, const float* __restrict__ el,
    float* __restrict__ A)
{
    __shared__ float redm[4][8];
    __shared__ float reds[4][8];
    int t0 = blockIdx.x * 4;
    int tid = threadIdx.x;
    int s0 = tid * 4;

    float4 u4[4], e4[4];
#pragma unroll
    for (int rr = 0; rr < 4; rr++) {
        u4[rr] = ((const float4*)(u + (size_t)(t0 + rr) * Nn))[tid];
        e4[rr] = ((const float4*)(el + (size_t)(t0 + rr) * Nn))[tid];
    }

    float v[4][4];
    float mx[4];
#pragma unroll
    for (int rr = 0; rr < 4; rr++) {
        float uu[4] = {u4[rr].x, u4[rr].y, u4[rr].z, u4[rr].w};
        float ee[4] = {e4[rr].x, e4[rr].y, e4[rr].z, e4[rr].w};
        mx[rr] = -3.4e38f;
#pragma unroll
        for (int i = 0; i < 4; i++) {
            float g = -__logf(-__logf(uu[i] + 1e-9f) + 1e-9f);
            float m = (s0 + i == t0 + rr) ? -1e9f : ee[i];
            v[rr][i] = (m + g) * 2.0f;   // / tau, tau = 0.5
            mx[rr] = fmaxf(mx[rr], v[rr][i]);
        }
    }
#pragma unroll
    for (int o = 16; o; o >>= 1)
#pragma unroll
        for (int rr = 0; rr < 4; rr++)
            mx[rr] = fmaxf(mx[rr], __shfl_xor_sync(0xffffffffu, mx[rr], o));
    if ((tid & 31) == 0)
#pragma unroll
        for (int rr = 0; rr < 4; rr++) redm[rr][tid >> 5] = mx[rr];
    __syncthreads();
    float bm[4];
#pragma unroll
    for (int rr = 0; rr < 4; rr++) {
        bm[rr] = redm[rr][0];
#pragma unroll
        for (int i = 1; i < 8; i++) bm[rr] = fmaxf(bm[rr], redm[rr][i]);
    }

    float sum[4];
#pragma unroll
    for (int rr = 0; rr < 4; rr++) {
        sum[rr] = 0.f;
#pragma unroll
        for (int i = 0; i < 4; i++) {
            v[rr][i] = __expf(v[rr][i] - bm[rr]);
            sum[rr] += v[rr][i];
        }
    }
#pragma unroll
    for (int o = 16; o; o >>= 1)
#pragma unroll
        for (int rr = 0; rr < 4; rr++)
            sum[rr] += __shfl_xor_sync(0xffffffffu, sum[rr], o);
    if ((tid & 31) == 0)
#pragma unroll
        for (int rr = 0; rr < 4; rr++) reds[rr][tid >> 5] = sum[rr];
    __syncthreads();
#pragma unroll
    for (int rr = 0; rr < 4; rr++) {
        float bs = reds[rr][0];
#pragma unroll
        for (int i = 1; i < 8; i++) bs += reds[rr][i];
        float inv = 1.0f / bs;
        ((float4*)(A + (size_t)(t0 + rr) * Nn))[tid] =
            make_float4(v[rr][0] * inv, v[rr][1] * inv,
                        v[rr][2] * inv, v[rr][3] * inv);
    }
}

// ============================================================
// K2: chained GEMMs, col-split across blockIdx.y:
//  h=0: ps = (es@Wp+bp) @ W1[:64]
//  h=1: ptb = (es@Wp+bp) @ W1[64:] + b1
// grid (128, 2) x 256, 16 rows/block, 40KB smem
// ============================================================
__global__ void __launch_bounds__(256) pspt_kernel(
    const float* __restrict__ es, const float* __restrict__ Wp,
    const float* __restrict__ bp, const float* __restrict__ W1,
    const float* __restrict__ b1)
{
    __shared__ __align__(16) float sW[64 * 64];    // W1 half, 16 KB
    __shared__ __align__(16) float sWp[64 * 64];   // 16 KB
    __shared__ __align__(16) float sE[16 * 64];
    __shared__ __align__(16) float sPr[16 * 64];
    int tid = threadIdx.x;
    int h = blockIdx.y;
    int row0 = blockIdx.x * 16;

    {
        const float4* w1h = (const float4*)(W1 + h * 4096);
        const float4* wp4 = (const float4*)Wp;
#pragma unroll
        for (int i = 0; i < 4; i++) {
            ((float4*)sW)[tid + i * 256]  = w1h[tid + i * 256];
            ((float4*)sWp)[tid + i * 256] = wp4[tid + i * 256];
        }
        ((float4*)sE)[tid] = ((const float4*)(es + row0 * 64))[tid];
    }
    __syncthreads();

    int r = tid >> 4;
    int q = (tid & 15) << 2;
    {
        float4 acc = *(const float4*)(bp + q);
        const float* er = sE + r * 64;
#pragma unroll
        for (int k = 0; k < 64; k++) {
            float e = er[k];
            float4 w = *(const float4*)(sWp + k * 64 + q);
            acc.x = fmaf(e, w.x, acc.x);
            acc.y = fmaf(e, w.y, acc.y);
            acc.z = fmaf(e, w.z, acc.z);
            acc.w = fmaf(e, w.w, acc.w);
        }
        *(float4*)(sPr + r * 64 + q) = acc;
    }
    __syncthreads();
    {
        float4 acc = h ? *(const float4*)(b1 + q)
                       : make_float4(0.f, 0.f, 0.f, 0.f);
        const float* pr = sPr + r * 64;
#pragma unroll
        for (int k = 0; k < 64; k++) {
            float p = pr[k];
            float4 w = *(const float4*)(sW + k * 64 + q);
            acc.x = fmaf(p, w.x, acc.x);
            acc.y = fmaf(p, w.y, acc.y);
            acc.z = fmaf(p, w.z, acc.z);
            acc.w = fmaf(p, w.w, acc.w);
        }
        float* dst = h ? g_ptb : g_ps;
        *(float4*)(dst + (row0 + r) * 64 + q) = acc;
    }
}

// ============================================================
// K3 (hot): hbar_tile = sum_{s in chunk} A[t,s]*relu(ps+ptb), then
//           hpart[c] = hbar_tile @ W2  (W2 folded in; commutes with chunk sum)
// grid (SCHUNKS, Nn/TT, Bn), 256 threads
// ============================================================
__global__ void __launch_bounds__(256) msg_agg_kernel(
    const float* __restrict__ A, const float* __restrict__ W2)
{
    __shared__ __align__(16) float sP[SC * 64];          // 16 KB: ps tile, then W2
    __shared__ __align__(16) float sA[SC * SA_STRIDE];   // 17.4 KB: A tile, then hbar
    int b  = blockIdx.z;
    int t0 = blockIdx.y * TT;
    int s0 = blockIdx.x * SC;
    int tid = threadIdx.x;

    {
        const float4* gp = (const float4*)(g_ps + (b * Nn + s0) * Dn);
        float4* sp4 = (float4*)sP;
#pragma unroll
        for (int i = 0; i < (SC * 16) / 256; i++)
            sp4[tid + i * 256] = gp[tid + i * 256];
#pragma unroll
        for (int k = 0; k < (TT * SC) / 256; k++) {
            int i = tid + k * 256;
            int sl = i & (SC - 1);
            int tl = i >> 6;           // / SC(=64)
            sA[sl * SA_STRIDE + tl] = A[(t0 + tl) * Nn + s0 + sl];
        }
    }
    __syncthreads();

    int q4 = (tid & 15) << 2;
    int tg = tid >> 4;
    int ta = t0 + tg * 4;

    u64t c[8];
#pragma unroll
    for (int i = 0; i < 4; i++) {
        float4 cv = *(const float4*)(g_ptb + (b * Nn + ta + i) * Dn + q4);
        c[2 * i]     = pack2(cv.x, cv.y);
        c[2 * i + 1] = pack2(cv.z, cv.w);
    }
    u64t acc[8];
#pragma unroll
    for (int i = 0; i < 8; i++) acc[i] = 0;

    const float4* pbase = ((const float4*)sP) + (tid & 15);
    const float4* abase = ((const float4*)sA) + tg;

#pragma unroll 8
    for (int s = 0; s < SC; s++) {
        float4 p  = pbase[s * 16];
        float4 av = abase[s * (SA_STRIDE / 4)];
        u64t pa = pack2(p.x, p.y);
        u64t pb = pack2(p.z, p.w);
        u64t a0 = pack2(av.x, av.x);
        u64t a1 = pack2(av.y, av.y);
        u64t a2 = pack2(av.z, av.z);
        u64t a3 = pack2(av.w, av.w);
        acc[0] = fma2(a0, relu2(add2(pa, c[0])), acc[0]);
        acc[1] = fma2(a0, relu2(add2(pb, c[1])), acc[1]);
        acc[2] = fma2(a1, relu2(add2(pa, c[2])), acc[2]);
        acc[3] = fma2(a1, relu2(add2(pb, c[3])), acc[3]);
        acc[4] = fma2(a2, relu2(add2(pa, c[4])), acc[4]);
        acc[5] = fma2(a2, relu2(add2(pb, c[5])), acc[5]);
        acc[6] = fma2(a3, relu2(add2(pa, c[6])), acc[6]);
        acc[7] = fma2(a3, relu2(add2(pb, c[7])), acc[7]);
    }

    // ---- stage hbar tile into sA [lt][d] (stride 68), load W2 into sP ----
    __syncthreads();   // main loop done reading sP/sA everywhere
    {
        int lt = tg * 4;   // local t rows lt..lt+3, col q4
#pragma unroll
        for (int i = 0; i < 4; i++) {
            float4 o;
            unpack2(acc[2 * i],     o.x, o.y);
            unpack2(acc[2 * i + 1], o.z, o.w);
            *(float4*)(sA + (lt + i) * SA_STRIDE + q4) = o;
        }
        const float4* w2g = (const float4*)W2;
#pragma unroll
        for (int i = 0; i < 4; i++)
            ((float4*)sP)[tid + i * 256] = w2g[tid + i * 256];
    }
    __syncthreads();

    // ---- GEMM: hpart[c,b,t0+r,:] = hbar_tile @ W2 ----
    // thread: r = tid>>2 (row), cb = tid&3; covers f4 cols cb, cb+4, cb+8, cb+12
    {
        int r  = tid >> 2;
        int cb = tid & 3;
        u64t g[8];
#pragma unroll
        for (int i = 0; i < 8; i++) g[i] = 0;
        const float* hr = sA + r * SA_STRIDE;
        const float4* w4 = (const float4*)sP;
#pragma unroll 8
        for (int k = 0; k < 64; k++) {
            float h = hr[k];
            u64t hh = pack2(h, h);
#pragma unroll
            for (int j = 0; j < 4; j++) {
                float4 w = w4[k * 16 + cb + 4 * j];
                g[2 * j]     = fma2(hh, pack2(w.x, w.y), g[2 * j]);
                g[2 * j + 1] = fma2(hh, pack2(w.z, w.w), g[2 * j + 1]);
            }
        }
        int cidx = blockIdx.x;
        float* hp = g_hpart + ((size_t)(cidx * Bn + b) * Nn + t0 + r) * Dn;
#pragma unroll
        for (int j = 0; j < 4; j++) {
            float4 o;
            unpack2(g[2 * j],     o.x, o.y);
            unpack2(g[2 * j + 1], o.z, o.w);
            *(float4*)(hp + (cb + 4 * j) * 4) = o;
        }
    }
}

// ============================================================
// K4: next_state = es + sum_c hpart[c] + b2   (pure streaming)
// 128 blocks x 256 thr, 1 float4 per thread, 16-way MLP
// ============================================================
__global__ void __launch_bounds__(256) out_kernel(
    const float* __restrict__ es, const float* __restrict__ b2,
    float* __restrict__ ns)
{
    int idx = blockIdx.x * 256 + threadIdx.x;   // f4 index, 0..32767
    float4 acc = ((const float4*)b2)[idx & 15];
    float4 e = ((const float4*)es)[idx];
    acc.x += e.x; acc.y += e.y; acc.z += e.z; acc.w += e.w;
#pragma unroll
    for (int c = 0; c < SCHUNKS; c++) {
        float4 v = ((const float4*)g_hpart)[(size_t)c * (Bn * Nn * 16) + idx];
        acc.x += v.x; acc.y += v.y; acc.z += v.z; acc.w += v.w;
    }
    ((float4*)ns)[idx] = acc;
}

// ============================================================
extern "C" void kernel_launch(void* const* d_in, const int* in_sizes, int n_in,
                              void* d_out, int out_size)
{
    const float* es = (const float*)d_in[0];
    const float* u  = (const float*)d_in[1];
    const float* Wp = (const float*)d_in[2];
    const float* bp = (const float*)d_in[3];
    const float* el = (const float*)d_in[4];
    const float* W1 = (const float*)d_in[5];
    const float* b1 = (const float*)d_in[6];
    const float* W2 = (const float*)d_in[7];
    const float* b2 = (const float*)d_in[8];

    float* outNS = (float*)d_out;                 // next_state [B,N,D]
    float* outA  = outNS + Bn * Nn * Dn;          // A [N,N]

    gumbel_softmax_kernel<<<Nn / 4, 256>>>(u, el, outA);
    pspt_kernel<<<dim3((Bn * Nn) / 16, 2), 256>>>(es, Wp, bp, W1, b1);
    msg_agg_kernel<<<dim3(SCHUNKS, Nn / TT, Bn), 256>>>(outA, W2);
    out_kernel<<<(Bn * Nn * Dn) / 4 / 256, 256>>>(es, b2, outNS);
}

// round 11
// speedup vs baseline: 1.4312x; 1.4312x over previous
#include <cuda_runtime.h>
#include <math.h>

#define Bn 2
#define Nn 1024
#define Dn 64
#define SCHUNKS 8           // s-dimension split for msg_agg
#define TT 64               // t-tile per block in msg_agg
#define SC (Nn / SCHUNKS)   // 128 s per block
#define SA_STRIDE 68        // padded [s][t] stride, float4-aligned

typedef unsigned long long u64t;

// -------- scratch (no malloc allowed) --------
__device__ float g_ps[Bn * Nn * Dn];
__device__ float g_ptb[Bn * Nn * Dn];
__device__ float g_hpart[SCHUNKS * Bn * Nn * Dn];

// ---------- packed f32x2 helpers ----------
__device__ __forceinline__ u64t pack2(float lo, float hi) {
    u64t r;
    asm("mov.b64 %0, {%1, %2};" : "=l"(r) : "f"(lo), "f"(hi));
    return r;
}
__device__ __forceinline__ void unpack2(u64t v, float& lo, float& hi) {
    asm("mov.b64 {%0, %1}, %2;" : "=f"(lo), "=f"(hi) : "l"(v));
}
__device__ __forceinline__ u64t add2(u64t a, u64t b) {
    u64t d;
    asm("add.rn.f32x2 %0, %1, %2;" : "=l"(d) : "l"(a), "l"(b));
    return d;
}
__device__ __forceinline__ u64t fma2(u64t a, u64t b, u64t c) {
    u64t d;
    asm("fma.rn.f32x2 %0, %1, %2, %3;" : "=l"(d) : "l"(a), "l"(b), "l"(c));
    return d;
}
__device__ __forceinline__ u64t relu2(u64t x) {
    u64t r;
    asm("{\n\t"
        ".reg .f32 lo, hi;\n\t"
        "mov.b64 {lo, hi}, %1;\n\t"
        "max.f32 lo, lo, 0f00000000;\n\t"
        "max.f32 hi, hi, 0f00000000;\n\t"
        "mov.b64 %0, {lo, hi};\n\t"
        "}" : "=l"(r) : "l"(x));
    return r;
}

// ============================================================
// K1: gumbel softmax, 2 rows per block (ILP), float4 I/O
// ============================================================
__global__ void __launch_bounds__(256) gumbel_softmax_kernel(
    const float* __restrict__ u, const float* __restrict__ el,
    float* __restrict__ A)
{
    __shared__ float redm[2][8];
    __shared__ float reds[2][8];
    int t0 = blockIdx.x * 2;
    int tid = threadIdx.x;
    int s0 = tid * 4;

    float4 u4a = ((const float4*)(u + (size_t)t0 * Nn))[tid];
    float4 u4b = ((const float4*)(u + (size_t)(t0 + 1) * Nn))[tid];
    float4 e4a = ((const float4*)(el + (size_t)t0 * Nn))[tid];
    float4 e4b = ((const float4*)(el + (size_t)(t0 + 1) * Nn))[tid];

    float va[4], vb[4];
    {
        float ua[4] = {u4a.x, u4a.y, u4a.z, u4a.w};
        float ub[4] = {u4b.x, u4b.y, u4b.z, u4b.w};
        float ea[4] = {e4a.x, e4a.y, e4a.z, e4a.w};
        float eb[4] = {e4b.x, e4b.y, e4b.z, e4b.w};
#pragma unroll
        for (int i = 0; i < 4; i++) {
            float ga = -__logf(-__logf(ua[i] + 1e-9f) + 1e-9f);
            float gb = -__logf(-__logf(ub[i] + 1e-9f) + 1e-9f);
            float ma = (s0 + i == t0)     ? -1e9f : ea[i];
            float mb = (s0 + i == t0 + 1) ? -1e9f : eb[i];
            va[i] = (ma + ga) * 2.0f;   // / tau, tau = 0.5
            vb[i] = (mb + gb) * 2.0f;
        }
    }
    float mxa = fmaxf(fmaxf(va[0], va[1]), fmaxf(va[2], va[3]));
    float mxb = fmaxf(fmaxf(vb[0], vb[1]), fmaxf(vb[2], vb[3]));
#pragma unroll
    for (int o = 16; o; o >>= 1) {
        mxa = fmaxf(mxa, __shfl_xor_sync(0xffffffffu, mxa, o));
        mxb = fmaxf(mxb, __shfl_xor_sync(0xffffffffu, mxb, o));
    }
    if ((tid & 31) == 0) { redm[0][tid >> 5] = mxa; redm[1][tid >> 5] = mxb; }
    __syncthreads();
    float bma = redm[0][0], bmb = redm[1][0];
#pragma unroll
    for (int i = 1; i < 8; i++) {
        bma = fmaxf(bma, redm[0][i]);
        bmb = fmaxf(bmb, redm[1][i]);
    }

    float suma = 0.f, sumb = 0.f;
#pragma unroll
    for (int i = 0; i < 4; i++) {
        va[i] = __expf(va[i] - bma); suma += va[i];
        vb[i] = __expf(vb[i] - bmb); sumb += vb[i];
    }
#pragma unroll
    for (int o = 16; o; o >>= 1) {
        suma += __shfl_xor_sync(0xffffffffu, suma, o);
        sumb += __shfl_xor_sync(0xffffffffu, sumb, o);
    }
    if ((tid & 31) == 0) { reds[0][tid >> 5] = suma; reds[1][tid >> 5] = sumb; }
    __syncthreads();
    float bsa = reds[0][0], bsb = reds[1][0];
#pragma unroll
    for (int i = 1; i < 8; i++) { bsa += reds[0][i]; bsb += reds[1][i]; }
    float inva = 1.0f / bsa, invb = 1.0f / bsb;

    ((float4*)(A + (size_t)t0 * Nn))[tid] =
        make_float4(va[0] * inva, va[1] * inva, va[2] * inva, va[3] * inva);
    ((float4*)(A + (size_t)(t0 + 1) * Nn))[tid] =
        make_float4(vb[0] * invb, vb[1] * invb, vb[2] * invb, vb[3] * invb);
}

// ============================================================
// K2: chained in-smem GEMMs: proj = es@Wp+bp;  ps = proj@W1[:64],
//     ptb = proj@W1[64:]+b1.  128 blocks x 16 rows, float4 fills.
// ============================================================
__global__ void __launch_bounds__(256) pspt_kernel(
    const float* __restrict__ es, const float* __restrict__ Wp,
    const float* __restrict__ bp, const float* __restrict__ W1,
    const float* __restrict__ b1)
{
    __shared__ __align__(16) float sW1[128 * 64];  // 32 KB
    __shared__ __align__(16) float sWp[64 * 64];   // 16 KB
    __shared__ __align__(16) float sE[16 * 64];
    __shared__ __align__(16) float sPr[16 * 64];
    int tid = threadIdx.x;
    int row0 = blockIdx.x * 16;

    {
        const float4* w1g = (const float4*)W1;
        const float4* wpg = (const float4*)Wp;
#pragma unroll
        for (int i = 0; i < 8; i++)
            ((float4*)sW1)[tid + i * 256] = w1g[tid + i * 256];
#pragma unroll
        for (int i = 0; i < 4; i++)
            ((float4*)sWp)[tid + i * 256] = wpg[tid + i * 256];
        ((float4*)sE)[tid] = ((const float4*)(es + row0 * 64))[tid];
    }
    __syncthreads();

    int r = tid >> 4;
    int q = (tid & 15) << 2;
    {
        float4 acc = *(const float4*)(bp + q);
        const float* er = sE + r * 64;
#pragma unroll
        for (int k = 0; k < 64; k++) {
            float e = er[k];
            float4 w = *(const float4*)(sWp + k * 64 + q);
            acc.x = fmaf(e, w.x, acc.x);
            acc.y = fmaf(e, w.y, acc.y);
            acc.z = fmaf(e, w.z, acc.z);
            acc.w = fmaf(e, w.w, acc.w);
        }
        *(float4*)(sPr + r * 64 + q) = acc;
    }
    __syncthreads();
    {
        float4 aps = make_float4(0.f, 0.f, 0.f, 0.f);
        float4 apt = *(const float4*)(b1 + q);
        const float* pr = sPr + r * 64;
#pragma unroll
        for (int k = 0; k < 64; k++) {
            float p = pr[k];
            float4 wa = *(const float4*)(sW1 + k * 64 + q);
            float4 wb = *(const float4*)(sW1 + (64 + k) * 64 + q);
            aps.x = fmaf(p, wa.x, aps.x);
            aps.y = fmaf(p, wa.y, aps.y);
            aps.z = fmaf(p, wa.z, aps.z);
            aps.w = fmaf(p, wa.w, aps.w);
            apt.x = fmaf(p, wb.x, apt.x);
            apt.y = fmaf(p, wb.y, apt.y);
            apt.z = fmaf(p, wb.z, apt.z);
            apt.w = fmaf(p, wb.w, apt.w);
        }
        *(float4*)(g_ps  + (row0 + r) * 64 + q) = aps;
        *(float4*)(g_ptb + (row0 + r) * 64 + q) = apt;
    }
}

// ============================================================
// K3 (hot): hpart[c,b,t,:] = sum_{s in chunk c} A[t,s]*relu(ps[b,s,:]+ptb[b,t,:])
// grid (SCHUNKS, Nn/TT, Bn) = (8,16,2) = 256 blocks, 256 threads
// ============================================================
__global__ void __launch_bounds__(256, 3) msg_agg_kernel(const float* __restrict__ A)
{
    __shared__ __align__(16) float sP[SC * 64];          // 32 KB [s][d]
    __shared__ __align__(16) float sA[SC * SA_STRIDE];   // 34.8 KB [s][t], padded
    int b  = blockIdx.z;
    int t0 = blockIdx.y * TT;
    int s0 = blockIdx.x * SC;
    int tid = threadIdx.x;

    {
        const float4* gp = (const float4*)(g_ps + (b * Nn + s0) * Dn);
        float4* sp4 = (float4*)sP;
#pragma unroll
        for (int i = 0; i < (SC * 16) / 256; i++)
            sp4[tid + i * 256] = gp[tid + i * 256];
#pragma unroll
        for (int k = 0; k < (TT * SC) / 256; k++) {
            int i = tid + k * 256;
            int sl = i & (SC - 1);
            int tl = i >> 7;           // / SC(=128)
            sA[sl * SA_STRIDE + tl] = A[(t0 + tl) * Nn + s0 + sl];
        }
    }
    __syncthreads();

    int q4 = (tid & 15) << 2;
    int tg = tid >> 4;
    int ta = t0 + tg * 4;

    u64t c[8];
#pragma unroll
    for (int i = 0; i < 4; i++) {
        float4 cv = *(const float4*)(g_ptb + (b * Nn + ta + i) * Dn + q4);
        c[2 * i]     = pack2(cv.x, cv.y);
        c[2 * i + 1] = pack2(cv.z, cv.w);
    }
    u64t acc[8];
#pragma unroll
    for (int i = 0; i < 8; i++) acc[i] = 0;

    const float4* pbase = ((const float4*)sP) + (tid & 15);
    const float4* abase = ((const float4*)sA) + tg;

#pragma unroll 8
    for (int s = 0; s < SC; s++) {
        float4 p  = pbase[s * 16];
        float4 av = abase[s * (SA_STRIDE / 4)];
        u64t pa = pack2(p.x, p.y);
        u64t pb = pack2(p.z, p.w);
        u64t a0 = pack2(av.x, av.x);
        u64t a1 = pack2(av.y, av.y);
        u64t a2 = pack2(av.z, av.z);
        u64t a3 = pack2(av.w, av.w);
        acc[0] = fma2(a0, relu2(add2(pa, c[0])), acc[0]);
        acc[1] = fma2(a0, relu2(add2(pb, c[1])), acc[1]);
        acc[2] = fma2(a1, relu2(add2(pa, c[2])), acc[2]);
        acc[3] = fma2(a1, relu2(add2(pb, c[3])), acc[3]);
        acc[4] = fma2(a2, relu2(add2(pa, c[4])), acc[4]);
        acc[5] = fma2(a2, relu2(add2(pb, c[5])), acc[5]);
        acc[6] = fma2(a3, relu2(add2(pa, c[6])), acc[6]);
        acc[7] = fma2(a3, relu2(add2(pb, c[7])), acc[7]);
    }

    int cidx = blockIdx.x;
    float* hp = g_hpart + ((size_t)(cidx * Bn + b) * Nn + ta) * Dn + q4;
#pragma unroll
    for (int i = 0; i < 4; i++) {
        float4 o;
        unpack2(acc[2 * i],     o.x, o.y);
        unpack2(acc[2 * i + 1], o.z, o.w);
        *(float4*)(hp + (size_t)i * Dn) = o;
    }
}

// ============================================================
// K4: hbar = sum_c hpart;  next_state = es + hbar @ W2 + b2
// 256 blocks x 256 thr, 8 rows/block; 2 threads cooperate per work item
// ============================================================
__global__ void __launch_bounds__(256) out_kernel(
    const float* __restrict__ es, const float* __restrict__ W2,
    const float* __restrict__ b2, float* __restrict__ ns)
{
    __shared__ __align__(16) float sW[64 * 64];   // 16 KB
    __shared__ __align__(16) float sH[8 * 64];    // 2 KB
    int tid = threadIdx.x;
    int row0 = blockIdx.x * 8;     // global row in [0, B*N)
    int half = tid & 1;

    {
        float4* w4 = (float4*)sW;
        const float4* g4 = (const float4*)W2;
#pragma unroll
        for (int i = 0; i < 4; i++) w4[tid + i * 256] = g4[tid + i * 256];
    }

    // Phase A: 128 float4 items (8 rows x 16), 2 threads/item, 4 chunks each
    {
        int item = tid >> 1;                 // 0..127
        int r  = item >> 4;
        int f4 = item & 15;
        size_t base = ((size_t)(row0 + r)) * 16 + f4;
        float4 acc = make_float4(0.f, 0.f, 0.f, 0.f);
#pragma unroll
        for (int j = 0; j < SCHUNKS / 2; j++) {
            int cc = half * (SCHUNKS / 2) + j;
            float4 v = ((const float4*)g_hpart)[(size_t)cc * (Bn * Nn * 16) + base];
            acc.x += v.x; acc.y += v.y; acc.z += v.z; acc.w += v.w;
        }
        acc.x += __shfl_xor_sync(0xffffffffu, acc.x, 1);
        acc.y += __shfl_xor_sync(0xffffffffu, acc.y, 1);
        acc.z += __shfl_xor_sync(0xffffffffu, acc.z, 1);
        acc.w += __shfl_xor_sync(0xffffffffu, acc.w, 1);
        if (!half) ((float4*)sH)[item] = acc;
    }
    __syncthreads();

    // Phase B: 128 outputs (8 rows x 16 float4), 2 threads/output, 32 k's each
    {
        int out = tid >> 1;                  // 0..127
        int r = out >> 4;
        int q = (out & 15) << 2;
        float4 acc = half ? make_float4(0.f, 0.f, 0.f, 0.f)
                          : *(const float4*)(b2 + q);
        const float* hr = sH + r * 64;
#pragma unroll
        for (int j = 0; j < 32; j++) {
            int k = half * 32 + j;
            float h = hr[k];
            float4 w = *(const float4*)(sW + k * 64 + q);
            acc.x = fmaf(h, w.x, acc.x);
            acc.y = fmaf(h, w.y, acc.y);
            acc.z = fmaf(h, w.z, acc.z);
            acc.w = fmaf(h, w.w, acc.w);
        }
        acc.x += __shfl_xor_sync(0xffffffffu, acc.x, 1);
        acc.y += __shfl_xor_sync(0xffffffffu, acc.y, 1);
        acc.z += __shfl_xor_sync(0xffffffffu, acc.z, 1);
        acc.w += __shfl_xor_sync(0xffffffffu, acc.w, 1);
        if (!half) {
            float4 e = *(const float4*)(es + ((size_t)(row0 + r)) * 64 + q);
            acc.x += e.x; acc.y += e.y; acc.z += e.z; acc.w += e.w;
            *(float4*)(ns + ((size_t)(row0 + r)) * 64 + q) = acc;
        }
    }
}

// ============================================================
extern "C" void kernel_launch(void* const* d_in, const int* in_sizes, int n_in,
                              void* d_out, int out_size)
{
    const float* es = (const float*)d_in[0];
    const float* u  = (const float*)d_in[1];
    const float* Wp = (const float*)d_in[2];
    const float* bp = (const float*)d_in[3];
    const float* el = (const float*)d_in[4];
    const float* W1 = (const float*)d_in[5];
    const float* b1 = (const float*)d_in[6];
    const float* W2 = (const float*)d_in[7];
    const float* b2 = (const float*)d_in[8];

    float* outNS = (float*)d_out;                 // next_state [B,N,D]
    float* outA  = outNS + Bn * Nn * Dn;          // A [N,N]

    gumbel_softmax_kernel<<<Nn / 2, 256>>>(u, el, outA);
    pspt_kernel<<<(Bn * Nn) / 16, 256>>>(es, Wp, bp, W1, b1);
    msg_agg_kernel<<<dim3(SCHUNKS, Nn / TT, Bn), 256>>>(outA);
    out_kernel<<<(Bn * Nn) / 8, 256>>>(es, W2, b2, outNS);
}